// round 3
// baseline (speedup 1.0000x reference)
#include <cuda_runtime.h>
#include <cstdint>

// RBF kernel, D=1 degenerate:
//   out[b,i,j] = exp( -(x1[b,i] - x2[b,j])^2 / (2*scale^2) )
// B=4, N1=N2=8192 -> 1.07 GB fp32 output, pure store-bandwidth bound.
//
// R3 changes vs R2 (143.8us, 89.8% DRAM):
//  - TI 8 -> 16: halves x2 L2 read traffic (134MB -> 67MB), fewer blocks.
//  - __stcs streaming stores: output is write-once; evict-first lets LTS
//    drain to DRAM without polluting L2 residency.
// Predicted: ~139us, DRAM% ~91-92.

static constexpr int B  = 4;
static constexpr int N1 = 8192;
static constexpr int N2 = 8192;
static constexpr int TI = 16;
static constexpr int TJ = 1024;   // 256 threads * float4

__global__ __launch_bounds__(256, 6)
void rbf_kernel(const float* __restrict__ x1,
                const float* __restrict__ x2,
                const float* __restrict__ scale,
                float* __restrict__ out)
{
    const int tid = threadIdx.x;
    const int jb  = blockIdx.x;        // 0..7
    const int it  = blockIdx.y;        // 0..511
    const int b   = blockIdx.z;        // 0..3

    const int j  = jb * TJ + tid * 4;
    const int i0 = it * TI;

    // x2 chunk for this thread (registers)
    const float4 v2 = *reinterpret_cast<const float4*>(x2 + (size_t)b * N2 + j);

    const float s = scale[0];
    const float c = -0.5f / (s * s);   // exp(c * d^2)

    const float* x1b = x1 + (size_t)b * N1 + i0;
    float* outb = out + ((size_t)b * N1 + i0) * (size_t)N2 + j;

    // Preload the 16 x1 values as 4x float4 (aligned: i0 % 16 == 0).
    float a[TI];
#pragma unroll
    for (int q = 0; q < TI / 4; ++q) {
        const float4 t = __ldg(reinterpret_cast<const float4*>(x1b + q * 4));
        a[q * 4 + 0] = t.x;
        a[q * 4 + 1] = t.y;
        a[q * 4 + 2] = t.z;
        a[q * 4 + 3] = t.w;
    }

#pragma unroll
    for (int r = 0; r < TI; ++r) {
        const float ar = a[r];
        const float dx0 = ar - v2.x;
        const float dx1 = ar - v2.y;
        const float dx2 = ar - v2.z;
        const float dx3 = ar - v2.w;
        float4 o;
        o.x = __expf(c * dx0 * dx0);
        o.y = __expf(c * dx1 * dx1);
        o.z = __expf(c * dx2 * dx2);
        o.w = __expf(c * dx3 * dx3);
        __stcs(reinterpret_cast<float4*>(outb + (size_t)r * N2), o);
    }
}

extern "C" void kernel_launch(void* const* d_in, const int* in_sizes, int n_in,
                              void* d_out, int out_size)
{
    const float* x1    = (const float*)d_in[0];
    const float* x2    = (const float*)d_in[1];
    const float* scale = (const float*)d_in[2];
    float* out         = (float*)d_out;

    dim3 grid(N2 / TJ, N1 / TI, B);   // (8, 512, 4)
    rbf_kernel<<<grid, 256>>>(x1, x2, scale, out);
}